// round 15
// baseline (speedup 1.0000x reference)
#include <cuda_runtime.h>
#include <cuda_bf16.h>
#include <math.h>

#define BS_   64
#define NQ_   300
#define T_    1280            // 64 * 20 targets
#define ROWS_ (BS_ * NQ_)     // 19200
#define RPB_  26              // 739 blocks; critical SM = 5 blocks = 130 rows
#define NBLK_ ((ROWS_ + RPB_ - 1) / RPB_)   // 739
#define THREADS_ 320          // 1280 cols / 4 per thread

__device__ __forceinline__ float frcp(float x) {
    float r;
    asm("rcp.approx.f32 %0, %1;" : "=f"(r) : "f"(x));
    return r;
}

// Element cost, modifier-safe (12 issued instructions incl. 1 MUFU):
//   dc2 = 2cx - 2tcx        FADD (neg free)
//   dw  = w - tw            FADD
//   S   = w + tw            FADD
//   A2  = max(dc2, -dc2)    FMNMX  (=|2*dcx|)
//   B   = max(dw, -dw)      FMNMX  (=|w-tw|)
//   M2  = max(A2, B)        FMNMX
//   num2= S - M2            FADD   (ratio num2/den2 == ri/enc, scale-invariant)
//   den2= S + M2            FADD
//   r   = rcp(den2)         MUFU
//   base= 0.5*A2 + B        FFMA   (L1 span = |dcx| + |dw|)
//   bf  = base + rc         FADD
//   v   = -num2*r + bf      FFMA
__device__ __forceinline__ float4 cost4(const float4 rd,
                                        const float* tcx2, const float* tw) {
    const float cx2 = rd.x, w = rd.y, rc = rd.z;
    float v[4];
#pragma unroll
    for (int i = 0; i < 4; ++i) {
        const float dc2  = cx2 - tcx2[i];
        const float dw   = w - tw[i];
        const float S    = w + tw[i];
        const float A2   = fmaxf(dc2, -dc2);
        const float B    = fmaxf(dw, -dw);
        const float M2   = fmaxf(A2, B);
        const float num2 = S - M2;
        const float den2 = S + M2;
        const float r    = frcp(den2);
        const float base = fmaf(0.5f, A2, B);
        const float bf   = base + rc;
        v[i] = fmaf(-num2, r, bf);
    }
    return make_float4(v[0], v[1], v[2], v[3]);
}

__global__ __launch_bounds__(THREADS_, 6)   // 32-reg cap -> up to 6 CTAs/SM
void hungarian_cost_kernel(const float* __restrict__ logits,   // [ROWS_, 2]
                           const float* __restrict__ spans,    // [ROWS_, 2] (cx, w)
                           const float* __restrict__ tgt,      // [T_, 2]    (cx, w)
                           const float* __restrict__ refp,     // [ROWS_, 2]
                           float* __restrict__ out)            // [ROWS_, T_]
{
    __shared__ float4 s_row[RPB_];   // {2cx, w, rc, pad}

    const int t    = threadIdx.x;          // owns columns 4t..4t+3
    const int row0 = blockIdx.x * RPB_;

    // ---- this thread's 4 target tuples: tcx2 = 2*tcx, tw ----
    const float4 ta = __ldg(reinterpret_cast<const float4*>(tgt) + 2 * t);
    const float4 tb = __ldg(reinterpret_cast<const float4*>(tgt) + 2 * t + 1);

    float tcx2[4], tw[4];
    tcx2[0] = 2.0f * ta.x; tw[0] = ta.y;
    tcx2[1] = 2.0f * ta.z; tw[1] = ta.w;
    tcx2[2] = 2.0f * tb.x; tw[2] = tb.y;
    tcx2[3] = 2.0f * tb.z; tw[3] = tb.w;

    // ---- cooperative per-row constants (threads 0..RPB_-1) ----
    if (t < RPB_) {
        const int r = row0 + t;
        if (r < ROWS_) {
            const float l0 = __ldg(logits + 2 * r);
            const float l1 = __ldg(logits + 2 * r + 1);
            const float m  = fmaxf(l0, l1);
            const float e0 = __expf(l0 - m);
            const float e1 = __expf(l1 - m);
            const float p0 = __fdividef(e0, e0 + e1);  // softmax prob class 0

            const float cx = __ldg(spans + 2 * r);
            const float w  = __ldg(spans + 2 * r + 1);
            const float hw = 0.5f * w;
            const float x1 = cx - hw;
            const float x2 = cx + hw;

            const float r0 = __ldg(refp + 2 * r);
            const float r1 = __ldg(refp + 2 * r + 1);
            const float d0 = fabsf(x1 - r0);
            const float d1 = fabsf(x2 - r1);
            const float cref = sqrtf(fmaf(d0, d0, d1 * d1));

            // rc = cost_reference - class_prob  (1D giou = num2/den2 exactly)
            s_row[t] = make_float4(2.0f * cx, w, cref - p0, 0.0f);
        }
    }
    __syncthreads();

    float4* const op = reinterpret_cast<float4*>(out + (size_t)row0 * T_) + t;

    if (row0 + RPB_ <= ROWS_) {
        // interior block: fully unrolled, immediate offsets, no guards
#pragma unroll
        for (int rr = 0; rr < RPB_; ++rr) {
            op[rr * (T_ / 4)] = cost4(s_row[rr], tcx2, tw);
        }
    } else {
        // tail block (row0 = 19188): 12 valid rows
#pragma unroll
        for (int rr = 0; rr < RPB_; ++rr) {
            if (row0 + rr < ROWS_) {
                op[rr * (T_ / 4)] = cost4(s_row[rr], tcx2, tw);
            }
        }
    }
}

extern "C" void kernel_launch(void* const* d_in, const int* in_sizes, int n_in,
                              void* d_out, int out_size) {
    const float* logits = (const float*)d_in[0];  // pred_logits [64,300,2]
    const float* spans  = (const float*)d_in[1];  // pred_spans  [64,300,2]
    const float* tgt    = (const float*)d_in[2];  // tgt_spans   [1280,2]
    const float* refp   = (const float*)d_in[3];  // ref_points  [64,300,2]
    float* out = (float*)d_out;                   // [64,300,1280] fp32

    hungarian_cost_kernel<<<NBLK_, THREADS_>>>(logits, spans, tgt, refp, out);
}

// round 16
// speedup vs baseline: 1.0093x; 1.0093x over previous
#include <cuda_runtime.h>
#include <cuda_bf16.h>
#include <math.h>

#define BS_   64
#define NQ_   300
#define T_    1280            // 64 * 20 targets
#define ROWS_ (BS_ * NQ_)     // 19200
#define RPB_  22              // 873 blocks (R14 geometry: occ 64%, issue 79%)
#define NBLK_ ((ROWS_ + RPB_ - 1) / RPB_)   // 873
#define THREADS_ 320          // 1280 cols / 4 per thread

__device__ __forceinline__ float frcp(float x) {
    float r;
    asm("rcp.approx.f32 %0, %1;" : "=f"(r) : "f"(x));
    return r;
}

// Element cost, modifier-safe (12 issued instructions incl. 1 MUFU):
//   dc2 = 2cx - 2tcx     FADD
//   dw  = w - tw         FADD
//   S   = w + tw         FADD
//   A2  = max(dc2,-dc2)  FMNMX (free neg)  = |2*dcx|
//   B   = max(dw,-dw)    FMNMX             = |w-tw|
//   M2  = max(A2,B)      FMNMX
//   num2= S - M2         FADD   (num2/den2 == ri/enc: 1D giou, scale-invariant)
//   den2= S + M2         FADD
//   r   = rcp(den2)      MUFU
//   base= 0.5*A2 + B     FFMA   (L1 span = |dcx| + |dw|)
//   bf  = base + rc      FADD
//   v   = -num2*r + bf   FFMA
__device__ __forceinline__ float4 cost4(const float4 rd,
                                        const float* tcx2, const float* tw) {
    const float cx2 = rd.x, w = rd.y, rc = rd.z;
    float v[4];
#pragma unroll
    for (int i = 0; i < 4; ++i) {
        const float dc2  = cx2 - tcx2[i];
        const float dw   = w - tw[i];
        const float S    = w + tw[i];
        const float A2   = fmaxf(dc2, -dc2);
        const float B    = fmaxf(dw, -dw);
        const float M2   = fmaxf(A2, B);
        const float num2 = S - M2;
        const float den2 = S + M2;
        const float r    = frcp(den2);
        const float base = fmaf(0.5f, A2, B);
        const float bf   = base + rc;
        v[i] = fmaf(-num2, r, bf);
    }
    return make_float4(v[0], v[1], v[2], v[3]);
}

__global__ __launch_bounds__(THREADS_, 6)   // 32-reg cap -> 6 CTAs/SM, 60 warps
void hungarian_cost_kernel(const float* __restrict__ logits,   // [ROWS_, 2]
                           const float* __restrict__ spans,    // [ROWS_, 2] (cx, w)
                           const float* __restrict__ tgt,      // [T_, 2]    (cx, w)
                           const float* __restrict__ refp,     // [ROWS_, 2]
                           float* __restrict__ out)            // [ROWS_, T_]
{
    __shared__ float4 s_row[RPB_];   // {2cx, w, rc, pad}

    const int t    = threadIdx.x;          // owns columns 4t..4t+3
    const int row0 = blockIdx.x * RPB_;

    // ---- this thread's 4 target tuples: tcx2 = 2*tcx, tw ----
    const float4 ta = __ldg(reinterpret_cast<const float4*>(tgt) + 2 * t);
    const float4 tb = __ldg(reinterpret_cast<const float4*>(tgt) + 2 * t + 1);

    float tcx2[4], tw[4];
    tcx2[0] = 2.0f * ta.x; tw[0] = ta.y;
    tcx2[1] = 2.0f * ta.z; tw[1] = ta.w;
    tcx2[2] = 2.0f * tb.x; tw[2] = tb.y;
    tcx2[3] = 2.0f * tb.z; tw[3] = tb.w;

    // ---- cooperative per-row constants (threads 0..RPB_-1) ----
    if (t < RPB_) {
        const int r = row0 + t;
        if (r < ROWS_) {
            const float l0 = __ldg(logits + 2 * r);
            const float l1 = __ldg(logits + 2 * r + 1);
            const float m  = fmaxf(l0, l1);
            const float e0 = __expf(l0 - m);
            const float e1 = __expf(l1 - m);
            const float p0 = __fdividef(e0, e0 + e1);  // softmax prob class 0

            const float cx = __ldg(spans + 2 * r);
            const float w  = __ldg(spans + 2 * r + 1);
            const float hw = 0.5f * w;
            const float x1 = cx - hw;
            const float x2 = cx + hw;

            const float r0 = __ldg(refp + 2 * r);
            const float r1 = __ldg(refp + 2 * r + 1);
            const float d0 = fabsf(x1 - r0);
            const float d1 = fabsf(x2 - r1);
            const float cref = sqrtf(fmaf(d0, d0, d1 * d1));

            // rc = cost_reference - class_prob  (1D giou = num2/den2 exactly)
            s_row[t] = make_float4(2.0f * cx, w, cref - p0, 0.0f);
        }
    }
    __syncthreads();

    float4* const op = reinterpret_cast<float4*>(out + (size_t)row0 * T_) + t;

    if (row0 + RPB_ <= ROWS_) {
        // interior block: fully unrolled, immediate offsets, no guards
#pragma unroll
        for (int rr = 0; rr < RPB_; ++rr) {
            op[rr * (T_ / 4)] = cost4(s_row[rr], tcx2, tw);
        }
    } else {
        // tail block (only block 872, row0 = 19184): 16 valid rows
#pragma unroll
        for (int rr = 0; rr < RPB_; ++rr) {
            if (row0 + rr < ROWS_) {
                op[rr * (T_ / 4)] = cost4(s_row[rr], tcx2, tw);
            }
        }
    }
}

extern "C" void kernel_launch(void* const* d_in, const int* in_sizes, int n_in,
                              void* d_out, int out_size) {
    const float* logits = (const float*)d_in[0];  // pred_logits [64,300,2]
    const float* spans  = (const float*)d_in[1];  // pred_spans  [64,300,2]
    const float* tgt    = (const float*)d_in[2];  // tgt_spans   [1280,2]
    const float* refp   = (const float*)d_in[3];  // ref_points  [64,300,2]
    float* out = (float*)d_out;                   // [64,300,1280] fp32

    hungarian_cost_kernel<<<NBLK_, THREADS_>>>(logits, spans, tgt, refp, out);
}

// round 17
// speedup vs baseline: 1.0637x; 1.0539x over previous
#include <cuda_runtime.h>
#include <cuda_bf16.h>
#include <math.h>

#define BS_   64
#define NQ_   300
#define T_    1280            // 64 * 20 targets
#define ROWS_ (BS_ * NQ_)     // 19200
#define RPB_  22              // 873 blocks: single wave at 6 CTAs/SM (888 slots)
#define NBLK_ ((ROWS_ + RPB_ - 1) / RPB_)   // 873
#define THREADS_ 320          // 1280 cols / 4 per thread

__device__ __forceinline__ float frcp(float x) {
    float r;
    asm("rcp.approx.f32 %0, %1;" : "=f"(r) : "f"(x));
    return r;
}

// R14-proven element body (10 slots + 1 MUFU), rcp issued early:
//   giou = (hs - M)/(hs + M),  M = max(|cx-tcx|, |hw-th|),  hs = hw+th
//   L1 span = |dc| + 2|e|;  rc = cref - p0 (folded row constant)
__device__ __forceinline__ float4 cost4(const float4 rd,
                                        const float* tcx, const float* th) {
    const float cx = rd.x, hw = rd.y, rc = rd.z;
    float4 o;
    float v[4];
#pragma unroll
    for (int i = 0; i < 4; ++i) {
        const float dc  = cx - tcx[i];
        const float e   = hw - th[i];
        const float hs  = hw + th[i];
        const float M   = fmaxf(fabsf(dc), fabsf(e));   // FMNMX, abs folded
        const float den = hs + M;
        const float r   = frcp(den);                    // MUFU early: latency
        const float num = hs - M;                       //   overlaps the chain below
        const float base = fmaf(2.0f, fabsf(e), fabsf(dc));
        const float bf   = base + rc;
        v[i] = fmaf(-num, r, bf);
    }
    o.x = v[0]; o.y = v[1]; o.z = v[2]; o.w = v[3];
    return o;
}

__global__ __launch_bounds__(THREADS_, 6)   // 32-reg cap -> 6 CTAs/SM, 60 warps
void hungarian_cost_kernel(const float* __restrict__ logits,   // [ROWS_, 2]
                           const float* __restrict__ spans,    // [ROWS_, 2] (cx, w)
                           const float* __restrict__ tgt,      // [T_, 2]    (cx, w)
                           const float* __restrict__ refp,     // [ROWS_, 2]
                           float* __restrict__ out)            // [ROWS_, T_]
{
    __shared__ float4 s_row[RPB_];   // {cx, hw, rc, pad}

    const int t    = threadIdx.x;          // owns columns 4t..4t+3
    const int row0 = blockIdx.x * RPB_;

    // ---- this thread's 4 target tuples: tcx, th = tw/2 ----
    const float4 ta = __ldg(reinterpret_cast<const float4*>(tgt) + 2 * t);
    const float4 tb = __ldg(reinterpret_cast<const float4*>(tgt) + 2 * t + 1);

    float tcx[4], th[4];
    tcx[0] = ta.x; th[0] = 0.5f * ta.y;
    tcx[1] = ta.z; th[1] = 0.5f * ta.w;
    tcx[2] = tb.x; th[2] = 0.5f * tb.y;
    tcx[3] = tb.z; th[3] = 0.5f * tb.w;

    // ---- cooperative per-row constants (threads 0..RPB_-1) ----
    if (t < RPB_) {
        const int r = row0 + t;
        if (r < ROWS_) {
            const float l0 = __ldg(logits + 2 * r);
            const float l1 = __ldg(logits + 2 * r + 1);
            const float m  = fmaxf(l0, l1);
            const float e0 = __expf(l0 - m);
            const float e1 = __expf(l1 - m);
            const float p0 = __fdividef(e0, e0 + e1);  // softmax prob class 0

            const float cx = __ldg(spans + 2 * r);
            const float w  = __ldg(spans + 2 * r + 1);
            const float hw = 0.5f * w;
            const float x1 = cx - hw;
            const float x2 = cx + hw;

            const float r0 = __ldg(refp + 2 * r);
            const float r1 = __ldg(refp + 2 * r + 1);
            const float d0 = fabsf(x1 - r0);
            const float d1 = fabsf(x2 - r1);
            const float cref = sqrtf(fmaf(d0, d0, d1 * d1));

            // rc = cost_reference - class_prob  (1D giou = num/den exactly)
            s_row[t] = make_float4(cx, hw, cref - p0, 0.0f);
        }
    }
    __syncthreads();

    float4* const op = reinterpret_cast<float4*>(out + (size_t)row0 * T_) + t;

    if (row0 + RPB_ <= ROWS_) {
        // interior block: fully unrolled, immediate offsets, no guards
#pragma unroll
        for (int rr = 0; rr < RPB_; ++rr) {
            op[rr * (T_ / 4)] = cost4(s_row[rr], tcx, th);
        }
    } else {
        // tail block (only block 872, row0 = 19184): 16 valid rows
#pragma unroll
        for (int rr = 0; rr < RPB_; ++rr) {
            if (row0 + rr < ROWS_) {
                op[rr * (T_ / 4)] = cost4(s_row[rr], tcx, th);
            }
        }
    }
}

extern "C" void kernel_launch(void* const* d_in, const int* in_sizes, int n_in,
                              void* d_out, int out_size) {
    const float* logits = (const float*)d_in[0];  // pred_logits [64,300,2]
    const float* spans  = (const float*)d_in[1];  // pred_spans  [64,300,2]
    const float* tgt    = (const float*)d_in[2];  // tgt_spans   [1280,2]
    const float* refp   = (const float*)d_in[3];  // ref_points  [64,300,2]
    float* out = (float*)d_out;                   // [64,300,1280] fp32

    hungarian_cost_kernel<<<NBLK_, THREADS_>>>(logits, spans, tgt, refp, out);
}